// round 9
// baseline (speedup 1.0000x reference)
#include <cuda_runtime.h>
#include <cuda_fp16.h>
#include <cstdint>
#include <math.h>

#define TT      8192
#define LSEQ    4096
#define NBATCH  2
#define DMODEL  2048
#define DINNER  4096
#define DSTATE  128
#define DCONV   4
#define NH      64
#define HD      64
#define CHUNKSZ 64
#define NCHUNK  64
#define CONVDIM 4352
#define DPROJ   8512
#define DT_OFF  8448
#define DPROJ_PAD 8576   // 67 * 128

#define K1  DMODEL        // 2048
#define K2  DINNER        // 4096

// ---------------- scratch ------------------------------------------------------
__device__ float gZX[(size_t)TT * DPROJ];
__device__ float gXC[(size_t)TT * CONVDIM];
__device__ float gYb[(size_t)TT * DINNER];
__device__ float gStates[(size_t)NBATCH * NCHUNK * NH * HD * DSTATE];
__device__ float gDt[TT * NH];
__device__ float gDalog[TT * NH];
__device__ float gAsum[NBATCH * NCHUNK * NH];

__device__ __half gA1[(size_t)TT * 2 * K1];        // [hi | lo]
__device__ __half gB1[(size_t)DPROJ_PAD * K1];     // single fp16
__device__ __half gA2[(size_t)TT * 2 * K2];        // [hi | lo]
__device__ __half gB2[(size_t)DMODEL * K2];        // single fp16

// ================= helpers ======================================================
__device__ __forceinline__ uint32_t smem_u32(const void* p) {
    uint32_t a;
    asm("{ .reg .u64 t; cvta.to.shared.u64 t, %1; cvt.u32.u64 %0, t; }" : "=r"(a) : "l"(p));
    return a;
}
__device__ __forceinline__ void cp16(uint32_t sa, const void* g) {
    asm volatile("cp.async.cg.shared.global [%0], [%1], 16;" :: "r"(sa), "l"(g));
}
__device__ __forceinline__ void ldmx4(uint32_t* r, uint32_t addr) {
    asm volatile("ldmatrix.sync.aligned.m8n8.x4.shared.b16 {%0,%1,%2,%3}, [%4];"
        : "=r"(r[0]), "=r"(r[1]), "=r"(r[2]), "=r"(r[3]) : "r"(addr));
}
__device__ __forceinline__ void mma16816(float* d, const uint32_t* a, const uint32_t* b) {
    asm volatile("mma.sync.aligned.m16n8k16.row.col.f32.f16.f16.f32 "
        "{%0,%1,%2,%3}, {%4,%5,%6,%7}, {%8,%9}, {%0,%1,%2,%3};"
        : "+f"(d[0]), "+f"(d[1]), "+f"(d[2]), "+f"(d[3])
        : "r"(a[0]), "r"(a[1]), "r"(a[2]), "r"(a[3]), "r"(b[0]), "r"(b[1]));
}

// ================= warp-MMA GEMM (R7 structure, 3 CTAs/SM) ======================
// C[m,n] = sum_k Ahi[m,k]*B[n,k] + Alo[m,k]*B[n,k].
// A layout: [M, 2K] = [hi | lo]; B layout: [N, K]; kb index wraps on B.
// BM=BN=128, BK=32. 8 warps: 2(M) x 4(N), warp 64x32. 3-stage cp.async.
#define ROWB 80                   // 32 halves + 8 pad
#define TILE_B (128*ROWB)         // 10240
#define STAGE_B (2*TILE_B)        // 20480
#define NSTG 3
#define GM_SMEM (NSTG*STAGE_B)    // 61440

__global__ __launch_bounds__(256, 3)
void gemm_mma_kernel(const __half* __restrict__ A, const __half* __restrict__ B,
                     float* __restrict__ C, int Nreal, int K)
{
    extern __shared__ char smem[];
    const uint32_t sb = smem_u32(smem);
    const int tid = threadIdx.x;
    const int wid = tid >> 5;
    const int lane = tid & 31;
    const int m0 = blockIdx.y * 128;
    const int n0 = blockIdx.x * 128;
    const int warp_m = wid & 1;
    const int warp_n = wid >> 1;
    const int NKBH = K >> 5;         // kb per limb
    const int NKB = 2 * NKBH;
    const int sA = 2 * K;

    float acc[4][4][4];
#pragma unroll
    for (int mi = 0; mi < 4; mi++)
#pragma unroll
        for (int ni = 0; ni < 4; ni++)
#pragma unroll
            for (int r = 0; r < 4; r++) acc[mi][ni][r] = 0.f;

    const int lrow = tid >> 2;
    const int lch  = tid & 3;
    auto load_stage = [&](int s, int kb) {
        int kbB = (kb >= NKBH) ? (kb - NKBH) : kb;
        uint32_t base = sb + s * STAGE_B;
        const __half* gA = A + (size_t)m0 * sA + (size_t)kb * 32;
        const __half* gB = B + (size_t)n0 * K + (size_t)kbB * 32;
#pragma unroll
        for (int i = 0; i < 2; i++) {
            int row = lrow + i * 64;
            cp16(base + row * ROWB + lch * 16, gA + (size_t)row * sA + lch * 8);
        }
#pragma unroll
        for (int i = 0; i < 2; i++) {
            int row = lrow + i * 64;
            cp16(base + TILE_B + row * ROWB + lch * 16, gB + (size_t)row * K + lch * 8);
        }
        asm volatile("cp.async.commit_group;" ::: "memory");
    };

    const int a_r  = lane & 15;
    const int a_kq = (lane >> 4) * 8;
    const int b_n  = ((lane >> 4) << 3) + (lane & 7);
    const int b_kq = ((lane >> 3) & 1) * 8;

    load_stage(0, 0);
    load_stage(1, 1 < NKB ? 1 : 0);

    for (int kb = 0; kb < NKB; kb++) {
        const int s = kb % NSTG;
        if (kb + 1 < NKB) asm volatile("cp.async.wait_group 1;" ::: "memory");
        else              asm volatile("cp.async.wait_group 0;" ::: "memory");
        __syncthreads();

        if (kb + 2 < NKB) load_stage((kb + 2) % NSTG, kb + 2);

        const uint32_t abase = sb + s * STAGE_B;
        const uint32_t bbase = abase + TILE_B;
#pragma unroll
        for (int ks = 0; ks < 2; ks++) {
            const int k0 = ks * 16;
            uint32_t af[4][4], bf[2][4];
#pragma unroll
            for (int mi = 0; mi < 4; mi++) {
                int m = warp_m * 64 + mi * 16 + a_r;
                ldmx4(af[mi], abase + m * ROWB + (k0 + a_kq) * 2);
            }
#pragma unroll
            for (int ni2 = 0; ni2 < 2; ni2++) {
                int n = warp_n * 32 + ni2 * 16 + b_n;
                ldmx4(bf[ni2], bbase + n * ROWB + (k0 + b_kq) * 2);
            }
#pragma unroll
            for (int mi = 0; mi < 4; mi++)
#pragma unroll
                for (int ni = 0; ni < 4; ni++)
                    mma16816(acc[mi][ni], af[mi], &bf[ni >> 1][(ni & 1) * 2]);
        }
    }

    const int er = lane >> 2;
    const int ec = (lane & 3) * 2;
#pragma unroll
    for (int mi = 0; mi < 4; mi++) {
#pragma unroll
        for (int ni = 0; ni < 4; ni++) {
            int col = n0 + warp_n * 32 + ni * 8 + ec;
            if (col < Nreal) {
                int row = m0 + warp_m * 64 + mi * 16 + er;
                float* p0 = C + (size_t)row * Nreal + col;
                p0[0] = acc[mi][ni][0];
                p0[1] = acc[mi][ni][1];
                float* p1 = p0 + (size_t)8 * Nreal;
                p1[0] = acc[mi][ni][2];
                p1[1] = acc[mi][ni][3];
            }
        }
    }
}

// ================= fp32 -> fp16 hi/lo split (A) and plain convert (B) ===========
__global__ __launch_bounds__(256)
void split_a_kernel(const float* __restrict__ src, __half* __restrict__ dst,
                    int kshift)
{
    size_t i = (size_t)blockIdx.x * blockDim.x + threadIdx.x;
    int K = 1 << kshift;
    int r = (int)(i >> kshift);
    int k = (int)(i & (K - 1));
    float x = src[i];
    __half hi = __float2half_rn(x);
    __half lo = __float2half_rn(x - __half2float(hi));
    size_t base = (size_t)r * 2 * K + k;
    dst[base] = hi; dst[base + K] = lo;
}

__global__ __launch_bounds__(256)
void convert_b_kernel(const float* __restrict__ src, __half* __restrict__ dst,
                      size_t n_src, size_t n_dst)
{
    size_t i = (size_t)blockIdx.x * blockDim.x + threadIdx.x;
    if (i >= n_dst) return;
    float x = (i < n_src) ? src[i] : 0.f;
    dst[i] = __float2half_rn(x);
}

// ================= pointwise ====================================================
__global__ __launch_bounds__(256)
void dt_kernel(const float* __restrict__ dt_bias, const float* __restrict__ A_log)
{
    int i = blockIdx.x * blockDim.x + threadIdx.x;
    if (i >= TT * NH) return;
    int h = i & (NH - 1);
    int t = i >> 6;
    float x = gZX[(size_t)t * DPROJ + DT_OFF + h] + dt_bias[h];
    float sp = (x > 20.f) ? x : log1pf(__expf(x));
    float A = -__expf(A_log[h]);
    gDt[i] = sp;
    gDalog[i] = sp * A;
}

__global__ __launch_bounds__(256)
void conv_kernel(const float* __restrict__ conv_w, const float* __restrict__ conv_b)
{
    int idx = blockIdx.x * blockDim.x + threadIdx.x;
    const int per_tok = CONVDIM / 4;
    if (idx >= TT * per_tok) return;
    int t  = idx / per_tok;
    int c4 = (idx - t * per_tok) * 4;
    int l  = t & (LSEQ - 1);

    float acc0 = conv_b[c4 + 0];
    float acc1 = conv_b[c4 + 1];
    float acc2 = conv_b[c4 + 2];
    float acc3 = conv_b[c4 + 3];
#pragma unroll
    for (int k = 0; k < DCONV; k++) {
        int lk = l - (DCONV - 1) + k;
        if (lk >= 0) {
            const float4 v = *(const float4*)&gZX[(size_t)(t - (DCONV - 1) + k) * DPROJ + DINNER + c4];
            acc0 += v.x * conv_w[(c4 + 0) * DCONV + k];
            acc1 += v.y * conv_w[(c4 + 1) * DCONV + k];
            acc2 += v.z * conv_w[(c4 + 2) * DCONV + k];
            acc3 += v.w * conv_w[(c4 + 3) * DCONV + k];
        }
    }
    float* o = &gXC[(size_t)t * CONVDIM + c4];
    o[0] = acc0 / (1.f + __expf(-acc0));
    o[1] = acc1 / (1.f + __expf(-acc1));
    o[2] = acc2 / (1.f + __expf(-acc2));
    o[3] = acc3 / (1.f + __expf(-acc3));
}

// ================= SSD: per-chunk kernel (transposed smem) ======================
#define LDT 68
#define LDB 132
#define CHUNK_SMEM ((2*128*LDT + 64*LDB + 2*64*LDT + 128) * 4)

__global__ __launch_bounds__(256)
void chunk_kernel()
{
    extern __shared__ float sm[];
    float* sBt  = sm;
    float* sCt  = sBt + 128 * LDT;
    float* sB   = sCt + 128 * LDT;
    float* sX   = sB + 64 * LDB;
    float* sMt  = sX + 64 * LDT;
    float* sAcs = sMt + 64 * LDT;
    float* sDec = sAcs + 64;

    const int bc = blockIdx.x;
    const int h  = blockIdx.y;
    const int tid = threadIdx.x;
    const int t0 = bc * CHUNKSZ;

    if (tid < 64) sAcs[tid] = gDalog[(size_t)(t0 + tid) * NH + h];
    __syncthreads();
    if (tid == 0) {
        float s = 0.f;
        for (int l = 0; l < 64; l++) { s += sAcs[l]; sAcs[l] = s; }
    }
    __syncthreads();
    if (tid < 64) sDec[tid] = __expf(sAcs[63] - sAcs[tid]);

    for (int i = tid; i < 2048; i += 256) {
        int s  = i & 63;
        int c4 = (i >> 6) << 2;
        const float* row = &gXC[(size_t)(t0 + s) * CONVDIM + DINNER];
        float4 vb = *(const float4*)(row + c4);
        float4 vc = *(const float4*)(row + DSTATE + c4);
        *(float4*)&sB[s * LDB + c4] = vb;
        sBt[(c4 + 0) * LDT + s] = vb.x; sBt[(c4 + 1) * LDT + s] = vb.y;
        sBt[(c4 + 2) * LDT + s] = vb.z; sBt[(c4 + 3) * LDT + s] = vb.w;
        sCt[(c4 + 0) * LDT + s] = vc.x; sCt[(c4 + 1) * LDT + s] = vc.y;
        sCt[(c4 + 2) * LDT + s] = vc.z; sCt[(c4 + 3) * LDT + s] = vc.w;
    }
    for (int i = tid; i < 1024; i += 256) {
        int s  = i & 63;
        int c4 = (i >> 6) << 2;
        float d = gDt[(size_t)(t0 + s) * NH + h];
        float4 v = *(const float4*)(&gXC[(size_t)(t0 + s) * CONVDIM + h * HD + c4]);
        v.x *= d; v.y *= d; v.z *= d; v.w *= d;
        *(float4*)&sX[s * LDT + c4] = v;
    }
    __syncthreads();

    const int tx = tid & 15;
    const int ty = tid >> 4;

    // Mt[s, l] = sum_n B[s,n] * C[l,n]
    {
        float acc[4][4];
#pragma unroll
        for (int i = 0; i < 4; i++)
#pragma unroll
            for (int j = 0; j < 4; j++) acc[i][j] = 0.f;
        for (int n = 0; n < 128; n++) {
            float4 a = *(const float4*)&sBt[n * LDT + ty * 4];
            float4 b = *(const float4*)&sCt[n * LDT + tx * 4];
            acc[0][0] += a.x * b.x; acc[0][1] += a.x * b.y; acc[0][2] += a.x * b.z; acc[0][3] += a.x * b.w;
            acc[1][0] += a.y * b.x; acc[1][1] += a.y * b.y; acc[1][2] += a.y * b.z; acc[1][3] += a.y * b.w;
            acc[2][0] += a.z * b.x; acc[2][1] += a.z * b.y; acc[2][2] += a.z * b.z; acc[2][3] += a.z * b.w;
            acc[3][0] += a.w * b.x; acc[3][1] += a.w * b.y; acc[3][2] += a.w * b.z; acc[3][3] += a.w * b.w;
        }
#pragma unroll
        for (int i = 0; i < 4; i++) {
            int s = ty * 4 + i;
#pragma unroll
            for (int j = 0; j < 4; j++) {
                int l = tx * 4 + j;
                sMt[s * LDT + l] = (s <= l) ? acc[i][j] * __expf(sAcs[l] - sAcs[s]) : 0.f;
            }
        }
    }
    __syncthreads();

    // Y[l,p] = sum_s M[l,s] * X[s,p]
    {
        float acc[4][4];
#pragma unroll
        for (int i = 0; i < 4; i++)
#pragma unroll
            for (int j = 0; j < 4; j++) acc[i][j] = 0.f;
        for (int s = 0; s < 64; s++) {
            float4 w = *(const float4*)&sMt[s * LDT + ty * 4];
            float4 x = *(const float4*)&sX[s * LDT + tx * 4];
            acc[0][0] += w.x * x.x; acc[0][1] += w.x * x.y; acc[0][2] += w.x * x.z; acc[0][3] += w.x * x.w;
            acc[1][0] += w.y * x.x; acc[1][1] += w.y * x.y; acc[1][2] += w.y * x.z; acc[1][3] += w.y * x.w;
            acc[2][0] += w.z * x.x; acc[2][1] += w.z * x.y; acc[2][2] += w.z * x.z; acc[2][3] += w.z * x.w;
            acc[3][0] += w.w * x.x; acc[3][1] += w.w * x.y; acc[3][2] += w.w * x.z; acc[3][3] += w.w * x.w;
        }
#pragma unroll
        for (int i = 0; i < 4; i++) {
            int l = ty * 4 + i;
#pragma unroll
            for (int j = 0; j < 4; j++)
                gYb[(size_t)(t0 + l) * DINNER + h * HD + tx * 4 + j] = acc[i][j];
        }
    }
    __syncthreads();

    for (int i = tid; i < 1024; i += 256) {
        int s = i >> 4, q = (i & 15) * 4;
        float d = sDec[s];
        float4 v = *(const float4*)&sX[s * LDT + q];
        v.x *= d; v.y *= d; v.z *= d; v.w *= d;
        *(float4*)&sX[s * LDT + q] = v;
    }
    __syncthreads();

    // states[p,n] = sum_s Xd[s,p] * B[s,n]
    {
        float st[4][8];
#pragma unroll
        for (int i = 0; i < 4; i++)
#pragma unroll
            for (int j = 0; j < 8; j++) st[i][j] = 0.f;
        const int pb = ty * 4, nb = tx * 8;
        for (int s = 0; s < 64; s++) {
            float4 xv = *(const float4*)&sX[s * LDT + pb];
            float4 b0 = *(const float4*)&sB[s * LDB + nb];
            float4 b1 = *(const float4*)&sB[s * LDB + nb + 4];
            float xa[4] = {xv.x, xv.y, xv.z, xv.w};
            float bb[8] = {b0.x, b0.y, b0.z, b0.w, b1.x, b1.y, b1.z, b1.w};
#pragma unroll
            for (int i = 0; i < 4; i++)
#pragma unroll
                for (int j = 0; j < 8; j++) st[i][j] += xa[i] * bb[j];
        }
        size_t base = ((size_t)bc * NH + h) * (HD * DSTATE);
#pragma unroll
        for (int i = 0; i < 4; i++)
#pragma unroll
            for (int j = 0; j < 8; j++)
                gStates[base + (size_t)(pb + i) * DSTATE + nb + j] = st[i][j];
    }

    if (tid == 0) gAsum[bc * NH + h] = sAcs[63];
}

// ================= inter-chunk scan =============================================
__global__ __launch_bounds__(512)
void scan_kernel()
{
    const int bh = blockIdx.x;
    const int b = bh >> 6, h = bh & 63;
    const int tid = threadIdx.x;
    const int off = tid * 16;

    float4 prev[4];
#pragma unroll
    for (int q = 0; q < 4; q++) prev[q] = make_float4(0.f, 0.f, 0.f, 0.f);

    for (int c = 0; c < NCHUNK; c++) {
        int bc = b * NCHUNK + c;
        size_t base = ((size_t)bc * NH + h) * (HD * DSTATE) + off;
        float dec = __expf(gAsum[bc * NH + h]);
        float4 cur[4];
#pragma unroll
        for (int q = 0; q < 4; q++) cur[q] = *(float4*)&gStates[base + q * 4];
#pragma unroll
        for (int q = 0; q < 4; q++) *(float4*)&gStates[base + q * 4] = prev[q];
#pragma unroll
        for (int q = 0; q < 4; q++) {
            prev[q].x = prev[q].x * dec + cur[q].x;
            prev[q].y = prev[q].y * dec + cur[q].y;
            prev[q].z = prev[q].z * dec + cur[q].z;
            prev[q].w = prev[q].w * dec + cur[q].w;
        }
    }
}

// ================= Y_off + skip + gating ========================================
#define YOFF_SMEM ((2*128*LDT + 64) * 4)

__global__ __launch_bounds__(256)
void yoff_kernel(const float* __restrict__ Dparam)
{
    extern __shared__ float sm[];
    float* sCt  = sm;
    float* sStT = sCt + 128 * LDT;
    float* sAcs = sStT + 128 * LDT;

    const int bc = blockIdx.x;
    const int h  = blockIdx.y;
    const int tid = threadIdx.x;
    const int t0 = bc * CHUNKSZ;

    if (tid < 64) sAcs[tid] = gDalog[(size_t)(t0 + tid) * NH + h];
    __syncthreads();
    if (tid == 0) {
        float s = 0.f;
        for (int l = 0; l < 64; l++) { s += sAcs[l]; sAcs[l] = s; }
    }

    for (int i = tid; i < 2048; i += 256) {
        int s  = i & 63;
        int c4 = (i >> 6) << 2;
        float4 vc = *(const float4*)(&gXC[(size_t)(t0 + s) * CONVDIM + DINNER + DSTATE + c4]);
        sCt[(c4 + 0) * LDT + s] = vc.x; sCt[(c4 + 1) * LDT + s] = vc.y;
        sCt[(c4 + 2) * LDT + s] = vc.z; sCt[(c4 + 3) * LDT + s] = vc.w;
        float4 vs = *(const float4*)(&gStates[(((size_t)bc * NH + h) * HD + s) * DSTATE + c4]);
        sStT[(c4 + 0) * LDT + s] = vs.x; sStT[(c4 + 1) * LDT + s] = vs.y;
        sStT[(c4 + 2) * LDT + s] = vs.z; sStT[(c4 + 3) * LDT + s] = vs.w;
    }
    __syncthreads();

    const int tx = tid & 15;
    const int ty = tid >> 4;

    float acc[4][4];
#pragma unroll
    for (int i = 0; i < 4; i++)
#pragma unroll
        for (int j = 0; j < 4; j++) acc[i][j] = 0.f;
    for (int n = 0; n < 128; n++) {
        float4 cv = *(const float4*)&sCt[n * LDT + ty * 4];
        float4 sv = *(const float4*)&sStT[n * LDT + tx * 4];
        acc[0][0] += cv.x * sv.x; acc[0][1] += cv.x * sv.y; acc[0][2] += cv.x * sv.z; acc[0][3] += cv.x * sv.w;
        acc[1][0] += cv.y * sv.x; acc[1][1] += cv.y * sv.y; acc[1][2] += cv.y * sv.z; acc[1][3] += cv.y * sv.w;
        acc[2][0] += cv.z * sv.x; acc[2][1] += cv.z * sv.y; acc[2][2] += cv.z * sv.z; acc[2][3] += cv.z * sv.w;
        acc[3][0] += cv.w * sv.x; acc[3][1] += cv.w * sv.y; acc[3][2] += cv.w * sv.z; acc[3][3] += cv.w * sv.w;
    }

    const float Dh = Dparam[h];
#pragma unroll
    for (int i = 0; i < 4; i++) {
        int l = ty * 4 + i;
        float sdo = __expf(sAcs[l]);
        size_t tz = (size_t)(t0 + l);
#pragma unroll
        for (int j = 0; j < 4; j++) {
            int p = tx * 4 + j;
            float x = gXC[tz * CONVDIM + h * HD + p];
            float z = gZX[tz * DPROJ + h * HD + p];
            float y = gYb[tz * DINNER + h * HD + p] + sdo * acc[i][j] + x * Dh;
            y *= z / (1.f + __expf(-z));
            gYb[tz * DINNER + h * HD + p] = y;
        }
    }
}

// ================= fused RMSNorm + fp16 hi/lo split =============================
__global__ __launch_bounds__(256)
void rms_split_kernel(const float* __restrict__ norm_w, __half* __restrict__ dst)
{
    const int t = blockIdx.x;
    const int tid = threadIdx.x;
    const float* y = &gYb[(size_t)t * DINNER];

    float ss = 0.f;
    for (int i = tid * 4; i < DINNER; i += 256 * 4) {
        float4 v = *(const float4*)(y + i);
        ss += v.x * v.x + v.y * v.y + v.z * v.z + v.w * v.w;
    }
#pragma unroll
    for (int o = 16; o > 0; o >>= 1) ss += __shfl_down_sync(0xffffffffu, ss, o);

    __shared__ float red[8];
    if ((tid & 31) == 0) red[tid >> 5] = ss;
    __syncthreads();
    if (tid == 0) {
        float tot = 0.f;
#pragma unroll
        for (int w = 0; w < 8; w++) tot += red[w];
        red[0] = rsqrtf(tot / (float)DINNER + 1e-5f);
    }
    __syncthreads();
    const float scale = red[0];

    __half* d0 = dst + (size_t)t * 2 * DINNER;
    for (int i = tid * 4; i < DINNER; i += 256 * 4) {
        float4 v = *(const float4*)(y + i);
        float4 w = *(const float4*)(norm_w + i);
        float a0 = v.x * scale * w.x, a1 = v.y * scale * w.y;
        float a2 = v.z * scale * w.z, a3 = v.w * scale * w.w;
        __half h0 = __float2half_rn(a0), h1 = __float2half_rn(a1);
        __half h2 = __float2half_rn(a2), h3 = __float2half_rn(a3);
        __half2 hA = __half2(h0, h1), hB = __half2(h2, h3);
        __half2 lA = __half2(__float2half_rn(a0 - __half2float(h0)),
                             __float2half_rn(a1 - __half2float(h1)));
        __half2 lB = __half2(__float2half_rn(a2 - __half2float(h2)),
                             __float2half_rn(a3 - __half2float(h3)));
        *(__half2*)(d0 + i)              = hA;
        *(__half2*)(d0 + i + 2)          = hB;
        *(__half2*)(d0 + DINNER + i)     = lA;
        *(__half2*)(d0 + DINNER + i + 2) = lB;
    }
}

// ================= launch =======================================================
extern "C" void kernel_launch(void* const* d_in, const int* in_sizes, int n_in,
                              void* d_out, int out_size)
{
    const float* u       = (const float*)d_in[0];
    const float* W_in    = (const float*)d_in[1];
    const float* conv_w  = (const float*)d_in[2];
    const float* conv_b  = (const float*)d_in[3];
    const float* dt_bias = (const float*)d_in[4];
    const float* A_log   = (const float*)d_in[5];
    const float* Dparam  = (const float*)d_in[6];
    const float* norm_w  = (const float*)d_in[7];
    const float* W_out   = (const float*)d_in[8];
    float* out = (float*)d_out;

    void *pZX, *pYb, *pA1, *pB1, *pA2, *pB2;
    cudaGetSymbolAddress(&pZX, gZX);
    cudaGetSymbolAddress(&pYb, gYb);
    cudaGetSymbolAddress(&pA1, gA1);
    cudaGetSymbolAddress(&pB1, gB1);
    cudaGetSymbolAddress(&pA2, gA2);
    cudaGetSymbolAddress(&pB2, gB2);

    cudaFuncSetAttribute(chunk_kernel, cudaFuncAttributeMaxDynamicSharedMemorySize, CHUNK_SMEM);
    cudaFuncSetAttribute(yoff_kernel,  cudaFuncAttributeMaxDynamicSharedMemorySize, YOFF_SMEM);
    cudaFuncSetAttribute(gemm_mma_kernel, cudaFuncAttributeMaxDynamicSharedMemorySize, GM_SMEM);

    // idx 0..2: operand prep (gemm1 lands at idx 3 for ncu)
    split_a_kernel<<<(int)(((size_t)TT * K1) / 256), 256>>>(u, (__half*)pA1, 11);
    convert_b_kernel<<<(int)(((size_t)DPROJ_PAD * K1 + 255) / 256), 256>>>(
        W_in, (__half*)pB1, (size_t)DPROJ * K1, (size_t)DPROJ_PAD * K1);
    convert_b_kernel<<<(int)(((size_t)DMODEL * K2 + 255) / 256), 256>>>(
        W_out, (__half*)pB2, (size_t)DMODEL * K2, (size_t)DMODEL * K2);

    // idx 3: in-projection
    {
        dim3 grid(DPROJ_PAD / 128, TT / 128);
        gemm_mma_kernel<<<grid, 256, GM_SMEM>>>((const __half*)pA1, (const __half*)pB1,
                                                (float*)pZX, DPROJ, K1);
    }
    dt_kernel<<<(TT * NH + 255) / 256, 256>>>(dt_bias, A_log);
    conv_kernel<<<(TT * (CONVDIM / 4) + 255) / 256, 256>>>(conv_w, conv_b);
    {
        dim3 grid(NBATCH * NCHUNK, NH);
        chunk_kernel<<<grid, 256, CHUNK_SMEM>>>();
    }
    scan_kernel<<<NBATCH * NH, 512>>>();
    {
        dim3 grid(NBATCH * NCHUNK, NH);
        yoff_kernel<<<grid, 256, YOFF_SMEM>>>(Dparam);
    }
    rms_split_kernel<<<TT, 256>>>(norm_w, (__half*)pA2);
    // out-projection
    {
        dim3 grid(DMODEL / 128, TT / 128);
        gemm_mma_kernel<<<grid, 256, GM_SMEM>>>((const __half*)pA2, (const __half*)pB2,
                                                out, DMODEL, K2);
    }
}

// round 10
// speedup vs baseline: 1.3849x; 1.3849x over previous
#include <cuda_runtime.h>
#include <cuda_fp16.h>
#include <cstdint>
#include <math.h>

#define TT      8192
#define LSEQ    4096
#define NBATCH  2
#define DMODEL  2048
#define DINNER  4096
#define DSTATE  128
#define DCONV   4
#define NH      64
#define HD      64
#define CHUNKSZ 64
#define NCHUNK  64
#define CONVDIM 4352
#define DPROJ   8512
#define DT_OFF  8448
#define DPROJ_PAD 8576   // 67 * 128

#define K1  DMODEL        // 2048
#define K2  DINNER        // 4096

// ---------------- scratch ------------------------------------------------------
__device__ float gZX[(size_t)TT * DPROJ];
__device__ float gXC[(size_t)TT * CONVDIM];
__device__ float gYb[(size_t)TT * DINNER];
__device__ float gStates[(size_t)NBATCH * NCHUNK * NH * HD * DSTATE];
__device__ float gDt[TT * NH];
__device__ float gDalog[TT * NH];
__device__ float gAsum[NBATCH * NCHUNK * NH];

__device__ __half gA1[(size_t)TT * K1];
__device__ __half gB1[(size_t)DPROJ_PAD * K1];
__device__ __half gA2[(size_t)TT * K2];
__device__ __half gB2[(size_t)DMODEL * K2];

// ================= helpers ======================================================
__device__ __forceinline__ uint32_t smem_u32(const void* p) {
    uint32_t a;
    asm("{ .reg .u64 t; cvta.to.shared.u64 t, %1; cvt.u32.u64 %0, t; }" : "=r"(a) : "l"(p));
    return a;
}
__device__ __forceinline__ void cp16(uint32_t sa, const void* g) {
    asm volatile("cp.async.cg.shared.global [%0], [%1], 16;" :: "r"(sa), "l"(g));
}
__device__ __forceinline__ void ldmx4(uint32_t* r, uint32_t addr) {
    asm volatile("ldmatrix.sync.aligned.m8n8.x4.shared.b16 {%0,%1,%2,%3}, [%4];"
        : "=r"(r[0]), "=r"(r[1]), "=r"(r[2]), "=r"(r[3]) : "r"(addr));
}
__device__ __forceinline__ void mma16816(float* d, const uint32_t* a, const uint32_t* b) {
    asm volatile("mma.sync.aligned.m16n8k16.row.col.f32.f16.f16.f32 "
        "{%0,%1,%2,%3}, {%4,%5,%6,%7}, {%8,%9}, {%0,%1,%2,%3};"
        : "+f"(d[0]), "+f"(d[1]), "+f"(d[2]), "+f"(d[3])
        : "r"(a[0]), "r"(a[1]), "r"(a[2]), "r"(a[3]), "r"(b[0]), "r"(b[1]));
}

// ================= warp-MMA GEMM (R7 structure, single fp16) ====================
// C[m,n] = sum_k A[m,k]*B[n,k]. BM=BN=128, BK=32.
// 8 warps: 2(M) x 4(N), warp 64x32. 3-stage cp.async.
#define ROWB 80                   // 32 halves + 8 pad
#define TILE_B (128*ROWB)         // 10240
#define STAGE_B (2*TILE_B)        // 20480
#define NSTG 3
#define GM_SMEM (NSTG*STAGE_B)    // 61440

__global__ __launch_bounds__(256)
void gemm_mma_kernel(const __half* __restrict__ A, const __half* __restrict__ B,
                     float* __restrict__ C, int Nreal, int K)
{
    extern __shared__ char smem[];
    const uint32_t sb = smem_u32(smem);
    const int tid = threadIdx.x;
    const int wid = tid >> 5;
    const int lane = tid & 31;
    const int m0 = blockIdx.y * 128;
    const int n0 = blockIdx.x * 128;
    const int warp_m = wid & 1;
    const int warp_n = wid >> 1;
    const int NKB = K >> 5;

    float acc[4][4][4];
#pragma unroll
    for (int mi = 0; mi < 4; mi++)
#pragma unroll
        for (int ni = 0; ni < 4; ni++)
#pragma unroll
            for (int r = 0; r < 4; r++) acc[mi][ni][r] = 0.f;

    const int lrow = tid >> 2;
    const int lch  = tid & 3;
    auto load_stage = [&](int s, int kb) {
        uint32_t base = sb + s * STAGE_B;
        const __half* gA = A + (size_t)m0 * K + (size_t)kb * 32;
        const __half* gB = B + (size_t)n0 * K + (size_t)kb * 32;
#pragma unroll
        for (int i = 0; i < 2; i++) {
            int row = lrow + i * 64;
            cp16(base + row * ROWB + lch * 16, gA + (size_t)row * K + lch * 8);
        }
#pragma unroll
        for (int i = 0; i < 2; i++) {
            int row = lrow + i * 64;
            cp16(base + TILE_B + row * ROWB + lch * 16, gB + (size_t)row * K + lch * 8);
        }
        asm volatile("cp.async.commit_group;" ::: "memory");
    };

    const int a_r  = lane & 15;
    const int a_kq = (lane >> 4) * 8;
    const int b_n  = ((lane >> 4) << 3) + (lane & 7);
    const int b_kq = ((lane >> 3) & 1) * 8;

    load_stage(0, 0);
    load_stage(1, 1 < NKB ? 1 : 0);

    for (int kb = 0; kb < NKB; kb++) {
        const int s = kb % NSTG;
        if (kb + 1 < NKB) asm volatile("cp.async.wait_group 1;" ::: "memory");
        else              asm volatile("cp.async.wait_group 0;" ::: "memory");
        __syncthreads();

        if (kb + 2 < NKB) load_stage((kb + 2) % NSTG, kb + 2);

        const uint32_t abase = sb + s * STAGE_B;
        const uint32_t bbase = abase + TILE_B;
#pragma unroll
        for (int ks = 0; ks < 2; ks++) {
            const int k0 = ks * 16;
            uint32_t af[4][4], bf[2][4];
#pragma unroll
            for (int mi = 0; mi < 4; mi++) {
                int m = warp_m * 64 + mi * 16 + a_r;
                ldmx4(af[mi], abase + m * ROWB + (k0 + a_kq) * 2);
            }
#pragma unroll
            for (int ni2 = 0; ni2 < 2; ni2++) {
                int n = warp_n * 32 + ni2 * 16 + b_n;
                ldmx4(bf[ni2], bbase + n * ROWB + (k0 + b_kq) * 2);
            }
#pragma unroll
            for (int mi = 0; mi < 4; mi++)
#pragma unroll
                for (int ni = 0; ni < 4; ni++)
                    mma16816(acc[mi][ni], af[mi], &bf[ni >> 1][(ni & 1) * 2]);
        }
    }

    const int er = lane >> 2;
    const int ec = (lane & 3) * 2;
#pragma unroll
    for (int mi = 0; mi < 4; mi++) {
#pragma unroll
        for (int ni = 0; ni < 4; ni++) {
            int col = n0 + warp_n * 32 + ni * 8 + ec;
            if (col < Nreal) {
                int row = m0 + warp_m * 64 + mi * 16 + er;
                float* p0 = C + (size_t)row * Nreal + col;
                p0[0] = acc[mi][ni][0];
                p0[1] = acc[mi][ni][1];
                float* p1 = p0 + (size_t)8 * Nreal;
                p1[0] = acc[mi][ni][2];
                p1[1] = acc[mi][ni][3];
            }
        }
    }
}

// ================= fp32 -> fp16 convert ========================================
__global__ __launch_bounds__(256)
void convert_kernel(const float* __restrict__ src, __half* __restrict__ dst,
                    size_t n_src, size_t n_dst)
{
    size_t i = (size_t)blockIdx.x * blockDim.x + threadIdx.x;
    if (i >= n_dst) return;
    float x = (i < n_src) ? src[i] : 0.f;
    dst[i] = __float2half_rn(x);
}

// ================= pointwise ====================================================
__global__ __launch_bounds__(256)
void dt_kernel(const float* __restrict__ dt_bias, const float* __restrict__ A_log)
{
    int i = blockIdx.x * blockDim.x + threadIdx.x;
    if (i >= TT * NH) return;
    int h = i & (NH - 1);
    int t = i >> 6;
    float x = gZX[(size_t)t * DPROJ + DT_OFF + h] + dt_bias[h];
    float sp = (x > 20.f) ? x : log1pf(__expf(x));
    float A = -__expf(A_log[h]);
    gDt[i] = sp;
    gDalog[i] = sp * A;
}

__global__ __launch_bounds__(256)
void conv_kernel(const float* __restrict__ conv_w, const float* __restrict__ conv_b)
{
    int idx = blockIdx.x * blockDim.x + threadIdx.x;
    const int per_tok = CONVDIM / 4;
    if (idx >= TT * per_tok) return;
    int t  = idx / per_tok;
    int c4 = (idx - t * per_tok) * 4;
    int l  = t & (LSEQ - 1);

    float acc0 = conv_b[c4 + 0];
    float acc1 = conv_b[c4 + 1];
    float acc2 = conv_b[c4 + 2];
    float acc3 = conv_b[c4 + 3];
#pragma unroll
    for (int k = 0; k < DCONV; k++) {
        int lk = l - (DCONV - 1) + k;
        if (lk >= 0) {
            const float4 v = *(const float4*)&gZX[(size_t)(t - (DCONV - 1) + k) * DPROJ + DINNER + c4];
            acc0 += v.x * conv_w[(c4 + 0) * DCONV + k];
            acc1 += v.y * conv_w[(c4 + 1) * DCONV + k];
            acc2 += v.z * conv_w[(c4 + 2) * DCONV + k];
            acc3 += v.w * conv_w[(c4 + 3) * DCONV + k];
        }
    }
    float* o = &gXC[(size_t)t * CONVDIM + c4];
    o[0] = acc0 / (1.f + __expf(-acc0));
    o[1] = acc1 / (1.f + __expf(-acc1));
    o[2] = acc2 / (1.f + __expf(-acc2));
    o[3] = acc3 / (1.f + __expf(-acc3));
}

// ================= SSD: per-chunk kernel (transposed smem) ======================
#define LDT 68
#define LDB 132
#define CHUNK_SMEM ((2*128*LDT + 64*LDB + 2*64*LDT + 128) * 4)

__global__ __launch_bounds__(256)
void chunk_kernel()
{
    extern __shared__ float sm[];
    float* sBt  = sm;
    float* sCt  = sBt + 128 * LDT;
    float* sB   = sCt + 128 * LDT;
    float* sX   = sB + 64 * LDB;
    float* sMt  = sX + 64 * LDT;
    float* sAcs = sMt + 64 * LDT;
    float* sDec = sAcs + 64;

    const int bc = blockIdx.x;
    const int h  = blockIdx.y;
    const int tid = threadIdx.x;
    const int t0 = bc * CHUNKSZ;

    if (tid < 64) sAcs[tid] = gDalog[(size_t)(t0 + tid) * NH + h];
    __syncthreads();
    if (tid == 0) {
        float s = 0.f;
        for (int l = 0; l < 64; l++) { s += sAcs[l]; sAcs[l] = s; }
    }
    __syncthreads();
    if (tid < 64) sDec[tid] = __expf(sAcs[63] - sAcs[tid]);

    for (int i = tid; i < 2048; i += 256) {
        int s  = i & 63;
        int c4 = (i >> 6) << 2;
        const float* row = &gXC[(size_t)(t0 + s) * CONVDIM + DINNER];
        float4 vb = *(const float4*)(row + c4);
        float4 vc = *(const float4*)(row + DSTATE + c4);
        *(float4*)&sB[s * LDB + c4] = vb;
        sBt[(c4 + 0) * LDT + s] = vb.x; sBt[(c4 + 1) * LDT + s] = vb.y;
        sBt[(c4 + 2) * LDT + s] = vb.z; sBt[(c4 + 3) * LDT + s] = vb.w;
        sCt[(c4 + 0) * LDT + s] = vc.x; sCt[(c4 + 1) * LDT + s] = vc.y;
        sCt[(c4 + 2) * LDT + s] = vc.z; sCt[(c4 + 3) * LDT + s] = vc.w;
    }
    for (int i = tid; i < 1024; i += 256) {
        int s  = i & 63;
        int c4 = (i >> 6) << 2;
        float d = gDt[(size_t)(t0 + s) * NH + h];
        float4 v = *(const float4*)(&gXC[(size_t)(t0 + s) * CONVDIM + h * HD + c4]);
        v.x *= d; v.y *= d; v.z *= d; v.w *= d;
        *(float4*)&sX[s * LDT + c4] = v;
    }
    __syncthreads();

    const int tx = tid & 15;
    const int ty = tid >> 4;

    // Mt[s, l] = sum_n B[s,n] * C[l,n]
    {
        float acc[4][4];
#pragma unroll
        for (int i = 0; i < 4; i++)
#pragma unroll
            for (int j = 0; j < 4; j++) acc[i][j] = 0.f;
        for (int n = 0; n < 128; n++) {
            float4 a = *(const float4*)&sBt[n * LDT + ty * 4];
            float4 b = *(const float4*)&sCt[n * LDT + tx * 4];
            acc[0][0] += a.x * b.x; acc[0][1] += a.x * b.y; acc[0][2] += a.x * b.z; acc[0][3] += a.x * b.w;
            acc[1][0] += a.y * b.x; acc[1][1] += a.y * b.y; acc[1][2] += a.y * b.z; acc[1][3] += a.y * b.w;
            acc[2][0] += a.z * b.x; acc[2][1] += a.z * b.y; acc[2][2] += a.z * b.z; acc[2][3] += a.z * b.w;
            acc[3][0] += a.w * b.x; acc[3][1] += a.w * b.y; acc[3][2] += a.w * b.z; acc[3][3] += a.w * b.w;
        }
#pragma unroll
        for (int i = 0; i < 4; i++) {
            int s = ty * 4 + i;
#pragma unroll
            for (int j = 0; j < 4; j++) {
                int l = tx * 4 + j;
                sMt[s * LDT + l] = (s <= l) ? acc[i][j] * __expf(sAcs[l] - sAcs[s]) : 0.f;
            }
        }
    }
    __syncthreads();

    // Y[l,p] = sum_s M[l,s] * X[s,p]
    {
        float acc[4][4];
#pragma unroll
        for (int i = 0; i < 4; i++)
#pragma unroll
            for (int j = 0; j < 4; j++) acc[i][j] = 0.f;
        for (int s = 0; s < 64; s++) {
            float4 w = *(const float4*)&sMt[s * LDT + ty * 4];
            float4 x = *(const float4*)&sX[s * LDT + tx * 4];
            acc[0][0] += w.x * x.x; acc[0][1] += w.x * x.y; acc[0][2] += w.x * x.z; acc[0][3] += w.x * x.w;
            acc[1][0] += w.y * x.x; acc[1][1] += w.y * x.y; acc[1][2] += w.y * x.z; acc[1][3] += w.y * x.w;
            acc[2][0] += w.z * x.x; acc[2][1] += w.z * x.y; acc[2][2] += w.z * x.z; acc[2][3] += w.z * x.w;
            acc[3][0] += w.w * x.x; acc[3][1] += w.w * x.y; acc[3][2] += w.w * x.z; acc[3][3] += w.w * x.w;
        }
#pragma unroll
        for (int i = 0; i < 4; i++) {
            int l = ty * 4 + i;
#pragma unroll
            for (int j = 0; j < 4; j++)
                gYb[(size_t)(t0 + l) * DINNER + h * HD + tx * 4 + j] = acc[i][j];
        }
    }
    __syncthreads();

    for (int i = tid; i < 1024; i += 256) {
        int s = i >> 4, q = (i & 15) * 4;
        float d = sDec[s];
        float4 v = *(const float4*)&sX[s * LDT + q];
        v.x *= d; v.y *= d; v.z *= d; v.w *= d;
        *(float4*)&sX[s * LDT + q] = v;
    }
    __syncthreads();

    // states[p,n] = sum_s Xd[s,p] * B[s,n]
    {
        float st[4][8];
#pragma unroll
        for (int i = 0; i < 4; i++)
#pragma unroll
            for (int j = 0; j < 8; j++) st[i][j] = 0.f;
        const int pb = ty * 4, nb = tx * 8;
        for (int s = 0; s < 64; s++) {
            float4 xv = *(const float4*)&sX[s * LDT + pb];
            float4 b0 = *(const float4*)&sB[s * LDB + nb];
            float4 b1 = *(const float4*)&sB[s * LDB + nb + 4];
            float xa[4] = {xv.x, xv.y, xv.z, xv.w};
            float bb[8] = {b0.x, b0.y, b0.z, b0.w, b1.x, b1.y, b1.z, b1.w};
#pragma unroll
            for (int i = 0; i < 4; i++)
#pragma unroll
                for (int j = 0; j < 8; j++) st[i][j] += xa[i] * bb[j];
        }
        size_t base = ((size_t)bc * NH + h) * (HD * DSTATE);
#pragma unroll
        for (int i = 0; i < 4; i++)
#pragma unroll
            for (int j = 0; j < 8; j++)
                gStates[base + (size_t)(pb + i) * DSTATE + nb + j] = st[i][j];
    }

    if (tid == 0) gAsum[bc * NH + h] = sAcs[63];
}

// ================= inter-chunk scan =============================================
__global__ __launch_bounds__(512)
void scan_kernel()
{
    const int bh = blockIdx.x;
    const int b = bh >> 6, h = bh & 63;
    const int tid = threadIdx.x;
    const int off = tid * 16;

    float4 prev[4];
#pragma unroll
    for (int q = 0; q < 4; q++) prev[q] = make_float4(0.f, 0.f, 0.f, 0.f);

    for (int c = 0; c < NCHUNK; c++) {
        int bc = b * NCHUNK + c;
        size_t base = ((size_t)bc * NH + h) * (HD * DSTATE) + off;
        float dec = __expf(gAsum[bc * NH + h]);
        float4 cur[4];
#pragma unroll
        for (int q = 0; q < 4; q++) cur[q] = *(float4*)&gStates[base + q * 4];
#pragma unroll
        for (int q = 0; q < 4; q++) *(float4*)&gStates[base + q * 4] = prev[q];
#pragma unroll
        for (int q = 0; q < 4; q++) {
            prev[q].x = prev[q].x * dec + cur[q].x;
            prev[q].y = prev[q].y * dec + cur[q].y;
            prev[q].z = prev[q].z * dec + cur[q].z;
            prev[q].w = prev[q].w * dec + cur[q].w;
        }
    }
}

// ================= Y_off + skip + gating ========================================
#define YOFF_SMEM ((2*128*LDT + 64) * 4)

__global__ __launch_bounds__(256)
void yoff_kernel(const float* __restrict__ Dparam)
{
    extern __shared__ float sm[];
    float* sCt  = sm;
    float* sStT = sCt + 128 * LDT;
    float* sAcs = sStT + 128 * LDT;

    const int bc = blockIdx.x;
    const int h  = blockIdx.y;
    const int tid = threadIdx.x;
    const int t0 = bc * CHUNKSZ;

    if (tid < 64) sAcs[tid] = gDalog[(size_t)(t0 + tid) * NH + h];
    __syncthreads();
    if (tid == 0) {
        float s = 0.f;
        for (int l = 0; l < 64; l++) { s += sAcs[l]; sAcs[l] = s; }
    }

    for (int i = tid; i < 2048; i += 256) {
        int s  = i & 63;
        int c4 = (i >> 6) << 2;
        float4 vc = *(const float4*)(&gXC[(size_t)(t0 + s) * CONVDIM + DINNER + DSTATE + c4]);
        sCt[(c4 + 0) * LDT + s] = vc.x; sCt[(c4 + 1) * LDT + s] = vc.y;
        sCt[(c4 + 2) * LDT + s] = vc.z; sCt[(c4 + 3) * LDT + s] = vc.w;
        float4 vs = *(const float4*)(&gStates[(((size_t)bc * NH + h) * HD + s) * DSTATE + c4]);
        sStT[(c4 + 0) * LDT + s] = vs.x; sStT[(c4 + 1) * LDT + s] = vs.y;
        sStT[(c4 + 2) * LDT + s] = vs.z; sStT[(c4 + 3) * LDT + s] = vs.w;
    }
    __syncthreads();

    const int tx = tid & 15;
    const int ty = tid >> 4;

    float acc[4][4];
#pragma unroll
    for (int i = 0; i < 4; i++)
#pragma unroll
        for (int j = 0; j < 4; j++) acc[i][j] = 0.f;
    for (int n = 0; n < 128; n++) {
        float4 cv = *(const float4*)&sCt[n * LDT + ty * 4];
        float4 sv = *(const float4*)&sStT[n * LDT + tx * 4];
        acc[0][0] += cv.x * sv.x; acc[0][1] += cv.x * sv.y; acc[0][2] += cv.x * sv.z; acc[0][3] += cv.x * sv.w;
        acc[1][0] += cv.y * sv.x; acc[1][1] += cv.y * sv.y; acc[1][2] += cv.y * sv.z; acc[1][3] += cv.y * sv.w;
        acc[2][0] += cv.z * sv.x; acc[2][1] += cv.z * sv.y; acc[2][2] += cv.z * sv.z; acc[2][3] += cv.z * sv.w;
        acc[3][0] += cv.w * sv.x; acc[3][1] += cv.w * sv.y; acc[3][2] += cv.w * sv.z; acc[3][3] += cv.w * sv.w;
    }

    const float Dh = Dparam[h];
#pragma unroll
    for (int i = 0; i < 4; i++) {
        int l = ty * 4 + i;
        float sdo = __expf(sAcs[l]);
        size_t tz = (size_t)(t0 + l);
#pragma unroll
        for (int j = 0; j < 4; j++) {
            int p = tx * 4 + j;
            float x = gXC[tz * CONVDIM + h * HD + p];
            float z = gZX[tz * DPROJ + h * HD + p];
            float y = gYb[tz * DINNER + h * HD + p] + sdo * acc[i][j] + x * Dh;
            y *= z / (1.f + __expf(-z));
            gYb[tz * DINNER + h * HD + p] = y;
        }
    }
}

// ================= fused RMSNorm + fp16 convert =================================
__global__ __launch_bounds__(256)
void rms_convert_kernel(const float* __restrict__ norm_w, __half* __restrict__ dst)
{
    const int t = blockIdx.x;
    const int tid = threadIdx.x;
    const float* y = &gYb[(size_t)t * DINNER];

    float ss = 0.f;
    for (int i = tid * 4; i < DINNER; i += 256 * 4) {
        float4 v = *(const float4*)(y + i);
        ss += v.x * v.x + v.y * v.y + v.z * v.z + v.w * v.w;
    }
#pragma unroll
    for (int o = 16; o > 0; o >>= 1) ss += __shfl_down_sync(0xffffffffu, ss, o);

    __shared__ float red[8];
    if ((tid & 31) == 0) red[tid >> 5] = ss;
    __syncthreads();
    if (tid == 0) {
        float tot = 0.f;
#pragma unroll
        for (int w = 0; w < 8; w++) tot += red[w];
        red[0] = rsqrtf(tot / (float)DINNER + 1e-5f);
    }
    __syncthreads();
    const float scale = red[0];

    __half* d0 = dst + (size_t)t * DINNER;
    for (int i = tid * 4; i < DINNER; i += 256 * 4) {
        float4 v = *(const float4*)(y + i);
        float4 w = *(const float4*)(norm_w + i);
        __half2 hA = __half2(__float2half_rn(v.x * scale * w.x),
                             __float2half_rn(v.y * scale * w.y));
        __half2 hB = __half2(__float2half_rn(v.z * scale * w.z),
                             __float2half_rn(v.w * scale * w.w));
        *(__half2*)(d0 + i)     = hA;
        *(__half2*)(d0 + i + 2) = hB;
    }
}

// ================= launch =======================================================
extern "C" void kernel_launch(void* const* d_in, const int* in_sizes, int n_in,
                              void* d_out, int out_size)
{
    const float* u       = (const float*)d_in[0];
    const float* W_in    = (const float*)d_in[1];
    const float* conv_w  = (const float*)d_in[2];
    const float* conv_b  = (const float*)d_in[3];
    const float* dt_bias = (const float*)d_in[4];
    const float* A_log   = (const float*)d_in[5];
    const float* Dparam  = (const float*)d_in[6];
    const float* norm_w  = (const float*)d_in[7];
    const float* W_out   = (const float*)d_in[8];
    float* out = (float*)d_out;

    void *pZX, *pYb, *pA1, *pB1, *pA2, *pB2;
    cudaGetSymbolAddress(&pZX, gZX);
    cudaGetSymbolAddress(&pYb, gYb);
    cudaGetSymbolAddress(&pA1, gA1);
    cudaGetSymbolAddress(&pB1, gB1);
    cudaGetSymbolAddress(&pA2, gA2);
    cudaGetSymbolAddress(&pB2, gB2);

    cudaFuncSetAttribute(chunk_kernel, cudaFuncAttributeMaxDynamicSharedMemorySize, CHUNK_SMEM);
    cudaFuncSetAttribute(yoff_kernel,  cudaFuncAttributeMaxDynamicSharedMemorySize, YOFF_SMEM);
    cudaFuncSetAttribute(gemm_mma_kernel, cudaFuncAttributeMaxDynamicSharedMemorySize, GM_SMEM);

    // idx 0..2: operand prep (gemm1 lands at idx 3 for ncu)
    convert_kernel<<<(int)(((size_t)TT * K1 + 255) / 256), 256>>>(
        u, (__half*)pA1, (size_t)TT * K1, (size_t)TT * K1);
    convert_kernel<<<(int)(((size_t)DPROJ_PAD * K1 + 255) / 256), 256>>>(
        W_in, (__half*)pB1, (size_t)DPROJ * K1, (size_t)DPROJ_PAD * K1);
    convert_kernel<<<(int)(((size_t)DMODEL * K2 + 255) / 256), 256>>>(
        W_out, (__half*)pB2, (size_t)DMODEL * K2, (size_t)DMODEL * K2);

    // idx 3: in-projection
    {
        dim3 grid(DPROJ_PAD / 128, TT / 128);
        gemm_mma_kernel<<<grid, 256, GM_SMEM>>>((const __half*)pA1, (const __half*)pB1,
                                                (float*)pZX, DPROJ, K1);
    }
    dt_kernel<<<(TT * NH + 255) / 256, 256>>>(dt_bias, A_log);
    conv_kernel<<<(TT * (CONVDIM / 4) + 255) / 256, 256>>>(conv_w, conv_b);
    {
        dim3 grid(NBATCH * NCHUNK, NH);
        chunk_kernel<<<grid, 256, CHUNK_SMEM>>>();
    }
    scan_kernel<<<NBATCH * NH, 512>>>();
    {
        dim3 grid(NBATCH * NCHUNK, NH);
        yoff_kernel<<<grid, 256, YOFF_SMEM>>>(Dparam);
    }
    rms_convert_kernel<<<TT, 256>>>(norm_w, (__half*)pA2);
    // out-projection
    {
        dim3 grid(DMODEL / 128, TT / 128);
        gemm_mma_kernel<<<grid, 256, GM_SMEM>>>((const __half*)pA2, (const __half*)pB2,
                                                out, DMODEL, K2);
    }
}